// round 16
// baseline (speedup 1.0000x reference)
#include <cuda_runtime.h>
#include <cuda_fp16.h>
#include <stdint.h>

// CPQuadRankLayer via mma.sync fp16. B=64, N=1024, C=4, R=64, D=O=128.
// R15 + double-buffered X/F staging (ONE sync per stage) + 1-term epilogue
// (merged-hi x single-fp16 fo). 256 thr, 2 CTAs/SM, warp tile 16b x 32r,
// ldmatrix fragments, x-prefetch, f LDG at stage start, smem f32 residual RMW,
// acc untouched until epilogue.

#define NN 1024

// smem byte offsets
#define BUFP     34816    // one staging buffer pair (XH 17408 + FH 17408)
#define XH_OFF   0        // within buffer: 64 rows x 272B fp16
#define FH_OFF   17408
#define RES_OFF  69632    // res[b][o] f32 accum: 64*128*4 = 32768
#define SS_OFF   102400   // ss[2][4][64] f32 = 2048
#define RINV_OFF 104448   // 64 f32
#define SMEM_BYTES 104704 // <= 113.5KB -> 2 CTAs/SM
// epilogue overlay (buffer 0; last readers fenced before use)
#define MH_OFF   0        // merged hi: 64 rows x 144B
#define FOH_OFF  9216     // fo^T: 128 rows x 144B -> ends 27648

__device__ __forceinline__ uint32_t smem_u32(const void* p) {
    uint32_t a;
    asm("{ .reg .u64 t; cvta.to.shared.u64 t, %1; cvt.u32.u64 %0, t; }" : "=r"(a) : "l"(p));
    return a;
}
__device__ __forceinline__ uint32_t packh2(float a, float b) {
    uint32_t r;   // low half = a, high half = b
    asm("cvt.rn.f16x2.f32 %0, %1, %2;" : "=r"(r) : "f"(b), "f"(a));
    return r;
}
__device__ __forceinline__ void mma_f16(float* c, const uint32_t* a, const uint32_t* b) {
    asm volatile(
        "mma.sync.aligned.m16n8k16.row.col.f32.f16.f16.f32 "
        "{%0,%1,%2,%3}, {%4,%5,%6,%7}, {%8,%9}, {%0,%1,%2,%3};"
        : "+f"(c[0]), "+f"(c[1]), "+f"(c[2]), "+f"(c[3])
        : "r"(a[0]), "r"(a[1]), "r"(a[2]), "r"(a[3]), "r"(b[0]), "r"(b[1]));
}
__device__ __forceinline__ void ldm_x4(uint32_t* r, uint32_t addr) {
    asm volatile("ldmatrix.sync.aligned.m8n8.x4.shared.b16 {%0,%1,%2,%3}, [%4];"
                 : "=r"(r[0]), "=r"(r[1]), "=r"(r[2]), "=r"(r[3]) : "r"(addr));
}

__global__ __launch_bounds__(256, 2)
void cpquad_mma12(const float* __restrict__ x, const float* __restrict__ f,
                  const float* __restrict__ fo, const float* __restrict__ gain,
                  float* __restrict__ out)
{
    extern __shared__ char sm[];
    const int n = blockIdx.x;
    const int t = threadIdx.x;
    const int lane = t & 31, wid = t >> 5;
    const int g = lane >> 2, tg = lane & 3;
    const int wb = wid >> 1, ws = wid & 1;   // b-tile (16 rows), r-half (32)
    const int bb = wb * 16;
    const uint32_t smb = smem_u32(sm);
    const float gn = __ldg(&gain[n]);

    // ldmatrix lane-address bases (tiles T00,T10,T01,T11), buffer-relative
    const uint32_t aBase = smb + XH_OFF + (uint32_t)(bb + (lane & 15)) * 272
                           + (uint32_t)((lane >> 4) << 4);
    const uint32_t bRow  = (uint32_t)(ws * 32 + (lane & 7) + ((lane >> 4) & 1) * 8);
    const uint32_t bCol  = (uint32_t)(((lane >> 3) & 1) << 4);
    const uint32_t bBase0 = smb + FH_OFF + bRow * 272 + bCol;   // nt 0,1
    const uint32_t bBase1 = bBase0 + 16 * 272;                  // nt 2,3

    float4 xr[8];
    float acc[4][4][4];
#pragma unroll
    for (int c = 0; c < 4; ++c)
#pragma unroll
        for (int nt = 0; nt < 4; ++nt)
#pragma unroll
            for (int u = 0; u < 4; ++u) acc[c][nt][u] = 0.0f;

    // prologue LDG x(0): thread rows {wid+8j}, float4 col = lane
#pragma unroll
    for (int j = 0; j < 8; ++j)
        xr[j] = *(const float4*)(x + (((size_t)(j * 8 + wid) * NN + n) * 4 + 0) * 128 + lane * 4);

#pragma unroll
    for (int c = 0; c < 4; ++c) {
        const uint32_t bsel = (uint32_t)(c & 1) * BUFP;
        // issue f(c) LDGs early; x STS + residual RMW cover part of the latency
        float4 fr[8];
#pragma unroll
        for (int j = 0; j < 8; ++j)
            fr[j] = *(const float4*)(f + (((size_t)c * NN + n) * 64 + (j * 8 + wid)) * 128 + lane * 4);

#pragma unroll
        for (int j = 0; j < 8; ++j) {
            const int row = j * 8 + wid;
            uint2 hi;
            hi.x = packh2(xr[j].x, xr[j].y);
            hi.y = packh2(xr[j].z, xr[j].w);
            *(uint2*)(sm + bsel + XH_OFF + row * 272 + lane * 8) = hi;
            float4* rp = (float4*)(sm + RES_OFF + row * 512 + lane * 16);
            if (c == 0) *rp = xr[j];
            else {
                float4 o = *rp;
                o.x += xr[j].x; o.y += xr[j].y; o.z += xr[j].z; o.w += xr[j].w;
                *rp = o;
            }
        }
#pragma unroll
        for (int j = 0; j < 8; ++j) {
            const int row = j * 8 + wid;
            uint2 hi;
            hi.x = packh2(fr[j].x, fr[j].y);
            hi.y = packh2(fr[j].z, fr[j].w);
            *(uint2*)(sm + bsel + FH_OFF + row * 272 + lane * 8) = hi;
        }
        __syncthreads();   // ONE sync per stage (double-buffered: overwrite-safe)

        // prefetch x(c+1): latency hides under the MMA block
        if (c < 3) {
#pragma unroll
            for (int j = 0; j < 8; ++j)
                xr[j] = *(const float4*)(x + (((size_t)(j * 8 + wid) * NN + n) * 4 + (c + 1)) * 128 + lane * 4);
        }

        // projection MMAs: 16b x 32r per warp, K=128; ldmatrix fragments
#pragma unroll
        for (int kk = 0; kk < 8; ++kk) {
            uint32_t ah[4], b0[4], b1[4];
            ldm_x4(ah, aBase + bsel + kk * 32);
            ldm_x4(b0, bBase0 + bsel + kk * 32);
            mma_f16(acc[c][0], ah, b0);
            mma_f16(acc[c][1], ah, b0 + 2);
            ldm_x4(b1, bBase1 + bsel + kk * 32);
            mma_f16(acc[c][2], ah, b1);
            mma_f16(acc[c][3], ah, b1 + 2);
        }
    }

    // ---- RMS partials: lane rows g, g+8; reduce over the 4 tg lanes ----
#pragma unroll
    for (int c = 0; c < 4; ++c) {
        float s0 = 0.f, s1 = 0.f;
#pragma unroll
        for (int nt = 0; nt < 4; ++nt) {
            s0 = fmaf(acc[c][nt][0], acc[c][nt][0], s0);
            s0 = fmaf(acc[c][nt][1], acc[c][nt][1], s0);
            s1 = fmaf(acc[c][nt][2], acc[c][nt][2], s1);
            s1 = fmaf(acc[c][nt][3], acc[c][nt][3], s1);
        }
        s0 += __shfl_xor_sync(0xffffffffu, s0, 1);
        s0 += __shfl_xor_sync(0xffffffffu, s0, 2);
        s1 += __shfl_xor_sync(0xffffffffu, s1, 1);
        s1 += __shfl_xor_sync(0xffffffffu, s1, 2);
        if (tg == 0) {
            *(float*)(sm + SS_OFF + (((ws * 4 + c) * 64) + bb + g) * 4)     = s0;
            *(float*)(sm + SS_OFF + (((ws * 4 + c) * 64) + bb + g + 8) * 4) = s1;
        }
    }
    __syncthreads();   // SS visible; all warps past MMA(3) (buffer 0 now free)

    // rinv-product per b (first 64 threads) + fo^T gather (single fp16) + STS
    if (t < 64) {
        float p = gn;
#pragma unroll
        for (int c = 0; c < 4; ++c) {
            float s = *(const float*)(sm + SS_OFF + ((0 * 4 + c) * 64 + t) * 4)
                    + *(const float*)(sm + SS_OFF + ((1 * 4 + c) * 64 + t) * 4);
            p *= rsqrtf(s * 0.015625f + 1e-6f);
        }
        *(float*)(sm + RINV_OFF + t * 4) = p;
    }
    {
        const int o = t >> 1, rh = (t & 1) * 32;
        const float* fob = fo + (size_t)n * 8192 + o;
#pragma unroll
        for (int u = 0; u < 8; ++u) {
            const int r0 = rh + u * 4;
            uint2 hi;
            hi.x = packh2(fob[(r0 + 0) * 128], fob[(r0 + 1) * 128]);
            hi.y = packh2(fob[(r0 + 2) * 128], fob[(r0 + 3) * 128]);
            *(uint2*)(sm + FOH_OFF + o * 144 + r0 * 2) = hi;
        }
    }
    __syncthreads();

    // merged = prod_c P * rinvprod  -> fp16 tile [b][r] (hi only)
    {
        const float r0v = *(const float*)(sm + RINV_OFF + (bb + g) * 4);
        const float r1v = *(const float*)(sm + RINV_OFF + (bb + g + 8) * 4);
#pragma unroll
        for (int nt = 0; nt < 4; ++nt) {
            const int rc = ws * 32 + nt * 8 + tg * 2;
            float m0 = acc[0][nt][0] * acc[1][nt][0] * acc[2][nt][0] * acc[3][nt][0] * r0v;
            float m1 = acc[0][nt][1] * acc[1][nt][1] * acc[2][nt][1] * acc[3][nt][1] * r0v;
            float m2 = acc[0][nt][2] * acc[1][nt][2] * acc[2][nt][2] * acc[3][nt][2] * r1v;
            float m3 = acc[0][nt][3] * acc[1][nt][3] * acc[2][nt][3] * acc[3][nt][3] * r1v;
            *(uint32_t*)(sm + MH_OFF + (bb + g) * 144 + rc * 2)     = packh2(m0, m1);
            *(uint32_t*)(sm + MH_OFF + (bb + g + 8) * 144 + rc * 2) = packh2(m2, m3);
        }
    }
    __syncthreads();

    // output GEMM: warp (wb, ws): 16b x 64o, K=64, 1 term (mh x foh)
    float acc2[8][4];
#pragma unroll
    for (int nt = 0; nt < 8; ++nt)
#pragma unroll
        for (int u = 0; u < 4; ++u) acc2[nt][u] = 0.0f;

    const int obase = ws * 64;
    const uint32_t mBase  = smb + MH_OFF + (uint32_t)(bb + (lane & 15)) * 144
                            + (uint32_t)((lane >> 4) << 4);
    const uint32_t foRow  = (uint32_t)(obase + (lane & 7) + ((lane >> 4) & 1) * 8);
    const uint32_t foBase = smb + FOH_OFF + foRow * 144 + (uint32_t)(((lane >> 3) & 1) << 4);

#pragma unroll
    for (int kk = 0; kk < 4; ++kk) {
        uint32_t ah[4];
        ldm_x4(ah, mBase + kk * 32);
#pragma unroll
        for (int p = 0; p < 4; ++p) {
            uint32_t bq[4];
            ldm_x4(bq, foBase + (uint32_t)(p * 16 * 144) + kk * 32);
            mma_f16(acc2[2 * p],     ah, bq);
            mma_f16(acc2[2 * p + 1], ah, bq + 2);
        }
    }

    // store with residual mean (res from smem accumulator)
#pragma unroll
    for (int nt = 0; nt < 8; ++nt) {
        const int oc = obase + nt * 8 + tg * 2;
        const int b0 = bb + g, b1 = bb + g + 8;
        const float2 r0 = *(const float2*)(sm + RES_OFF + (b0 * 128 + oc) * 4);
        const float2 r1 = *(const float2*)(sm + RES_OFF + (b1 * 128 + oc) * 4);
        float2 o0, o1;
        o0.x = acc2[nt][0] + 0.25f * r0.x;
        o0.y = acc2[nt][1] + 0.25f * r0.y;
        o1.x = acc2[nt][2] + 0.25f * r1.x;
        o1.y = acc2[nt][3] + 0.25f * r1.y;
        *(float2*)(out + ((size_t)b0 * NN + n) * 128 + oc) = o0;
        *(float2*)(out + ((size_t)b1 * NN + n) * 128 + oc) = o1;
    }
}

extern "C" void kernel_launch(void* const* d_in, const int* in_sizes, int n_in,
                              void* d_out, int out_size)
{
    const float* x       = (const float*)d_in[0];
    const float* factors = (const float*)d_in[1];
    const float* fo      = (const float*)d_in[2];
    const float* gain    = (const float*)d_in[3];
    float* out = (float*)d_out;

    cudaFuncSetAttribute(cpquad_mma12, cudaFuncAttributeMaxDynamicSharedMemorySize, SMEM_BYTES);
    cpquad_mma12<<<NN, 256, SMEM_BYTES>>>(x, factors, fo, gain, out);
}

// round 17
// speedup vs baseline: 1.1284x; 1.1284x over previous
#include <cuda_runtime.h>
#include <cuda_fp16.h>
#include <stdint.h>

// CPQuadRankLayer via mma.sync fp16. B=64, N=1024, C=4, R=64, D=O=128.
// R15 structure verbatim (256 thr, 2 CTAs/SM, warp tile 16b x 32r, single-buffered
// staging w/ two syncs per stage, x-prefetch, f LDG at stage start, ldmatrix
// fragments, smem f32 residual RMW, acc untouched until epilogue).
// Only change vs R15: 1-term epilogue (merged-hi x single-fp16 fo), ML tile gone.

#define NN 1024

// smem byte offsets (mainloop)
#define XH_OFF   0        // 64 rows x 272B (128 fp16 + pad)
#define FH_OFF   17408
// epilogue overlay (over X/F region, dead after mainloop)
#define MH_OFF   0        // merged hi: 64 rows x 144B
#define FOH_OFF  9216     // fo^T: 128 rows x 144B -> ends 27648
#define RES_OFF  36864    // res[b][o] f32 accum: 64*128*4 = 32768 (live in mainloop)
#define SS_OFF   69632    // ss[2][4][64] f32 = 2048
#define RINV_OFF 71680    // 64 f32
#define SMEM_BYTES 71936  // 2 CTAs/SM

__device__ __forceinline__ uint32_t smem_u32(const void* p) {
    uint32_t a;
    asm("{ .reg .u64 t; cvta.to.shared.u64 t, %1; cvt.u32.u64 %0, t; }" : "=r"(a) : "l"(p));
    return a;
}
__device__ __forceinline__ uint32_t packh2(float a, float b) {
    uint32_t r;   // low half = a, high half = b
    asm("cvt.rn.f16x2.f32 %0, %1, %2;" : "=r"(r) : "f"(b), "f"(a));
    return r;
}
__device__ __forceinline__ void mma_f16(float* c, const uint32_t* a, const uint32_t* b) {
    asm volatile(
        "mma.sync.aligned.m16n8k16.row.col.f32.f16.f16.f32 "
        "{%0,%1,%2,%3}, {%4,%5,%6,%7}, {%8,%9}, {%0,%1,%2,%3};"
        : "+f"(c[0]), "+f"(c[1]), "+f"(c[2]), "+f"(c[3])
        : "r"(a[0]), "r"(a[1]), "r"(a[2]), "r"(a[3]), "r"(b[0]), "r"(b[1]));
}
__device__ __forceinline__ void ldm_x4(uint32_t* r, uint32_t addr) {
    asm volatile("ldmatrix.sync.aligned.m8n8.x4.shared.b16 {%0,%1,%2,%3}, [%4];"
                 : "=r"(r[0]), "=r"(r[1]), "=r"(r[2]), "=r"(r[3]) : "r"(addr));
}

__global__ __launch_bounds__(256, 2)
void cpquad_mma13(const float* __restrict__ x, const float* __restrict__ f,
                  const float* __restrict__ fo, const float* __restrict__ gain,
                  float* __restrict__ out)
{
    extern __shared__ char sm[];
    const int n = blockIdx.x;
    const int t = threadIdx.x;
    const int lane = t & 31, wid = t >> 5;
    const int g = lane >> 2, tg = lane & 3;
    const int wb = wid >> 1, ws = wid & 1;   // b-tile (16 rows), r-half (32)
    const int bb = wb * 16;
    const uint32_t smb = smem_u32(sm);
    const float gn = __ldg(&gain[n]);

    // ldmatrix lane-address bases (tiles T00,T10,T01,T11 order)
    const uint32_t aBase = smb + XH_OFF + (uint32_t)(bb + (lane & 15)) * 272
                           + (uint32_t)((lane >> 4) << 4);
    const uint32_t bRow  = (uint32_t)(ws * 32 + (lane & 7) + ((lane >> 4) & 1) * 8);
    const uint32_t bCol  = (uint32_t)(((lane >> 3) & 1) << 4);
    const uint32_t bBase0 = smb + FH_OFF + bRow * 272 + bCol;   // nt 0,1
    const uint32_t bBase1 = bBase0 + 16 * 272;                  // nt 2,3

    float4 xr[8];
    float acc[4][4][4];
#pragma unroll
    for (int c = 0; c < 4; ++c)
#pragma unroll
        for (int nt = 0; nt < 4; ++nt)
#pragma unroll
            for (int u = 0; u < 4; ++u) acc[c][nt][u] = 0.0f;

    // prologue LDG x(0): thread rows {wid+8j}, float4 col = lane
#pragma unroll
    for (int j = 0; j < 8; ++j)
        xr[j] = *(const float4*)(x + (((size_t)(j * 8 + wid) * NN + n) * 4 + 0) * 128 + lane * 4);

#pragma unroll
    for (int c = 0; c < 4; ++c) {
        // issue f(c) LDGs early, then x STS + residual RMW while f is in flight
        float4 fr[8];
#pragma unroll
        for (int j = 0; j < 8; ++j)
            fr[j] = *(const float4*)(f + (((size_t)c * NN + n) * 64 + (j * 8 + wid)) * 128 + lane * 4);

#pragma unroll
        for (int j = 0; j < 8; ++j) {
            const int row = j * 8 + wid;
            uint2 hi;
            hi.x = packh2(xr[j].x, xr[j].y);
            hi.y = packh2(xr[j].z, xr[j].w);
            *(uint2*)(sm + XH_OFF + row * 272 + lane * 8) = hi;
            float4* rp = (float4*)(sm + RES_OFF + row * 512 + lane * 16);
            if (c == 0) *rp = xr[j];
            else {
                float4 o = *rp;
                o.x += xr[j].x; o.y += xr[j].y; o.z += xr[j].z; o.w += xr[j].w;
                *rp = o;
            }
        }
#pragma unroll
        for (int j = 0; j < 8; ++j) {
            const int row = j * 8 + wid;
            uint2 hi;
            hi.x = packh2(fr[j].x, fr[j].y);
            hi.y = packh2(fr[j].z, fr[j].w);
            *(uint2*)(sm + FH_OFF + row * 272 + lane * 8) = hi;
        }
        __syncthreads();

        // prefetch x(c+1): latency hides under the MMA block
        if (c < 3) {
#pragma unroll
            for (int j = 0; j < 8; ++j)
                xr[j] = *(const float4*)(x + (((size_t)(j * 8 + wid) * NN + n) * 4 + (c + 1)) * 128 + lane * 4);
        }

        // projection MMAs: 16b x 32r per warp, K=128; ldmatrix fragments
#pragma unroll
        for (int kk = 0; kk < 8; ++kk) {
            uint32_t ah[4], b0[4], b1[4];
            ldm_x4(ah, aBase + kk * 32);
            ldm_x4(b0, bBase0 + kk * 32);
            mma_f16(acc[c][0], ah, b0);
            mma_f16(acc[c][1], ah, b0 + 2);
            ldm_x4(b1, bBase1 + kk * 32);
            mma_f16(acc[c][2], ah, b1);
            mma_f16(acc[c][3], ah, b1 + 2);
        }
        __syncthreads();
    }

    // ---- RMS partials: lane rows g, g+8; reduce over the 4 tg lanes ----
#pragma unroll
    for (int c = 0; c < 4; ++c) {
        float s0 = 0.f, s1 = 0.f;
#pragma unroll
        for (int nt = 0; nt < 4; ++nt) {
            s0 = fmaf(acc[c][nt][0], acc[c][nt][0], s0);
            s0 = fmaf(acc[c][nt][1], acc[c][nt][1], s0);
            s1 = fmaf(acc[c][nt][2], acc[c][nt][2], s1);
            s1 = fmaf(acc[c][nt][3], acc[c][nt][3], s1);
        }
        s0 += __shfl_xor_sync(0xffffffffu, s0, 1);
        s0 += __shfl_xor_sync(0xffffffffu, s0, 2);
        s1 += __shfl_xor_sync(0xffffffffu, s1, 1);
        s1 += __shfl_xor_sync(0xffffffffu, s1, 2);
        if (tg == 0) {
            *(float*)(sm + SS_OFF + (((ws * 4 + c) * 64) + bb + g) * 4)     = s0;
            *(float*)(sm + SS_OFF + (((ws * 4 + c) * 64) + bb + g + 8) * 4) = s1;
        }
    }
    __syncthreads();

    // rinv-product per b (first 64 threads) + fo^T gather (single fp16) + STS
    if (t < 64) {
        float p = gn;
#pragma unroll
        for (int c = 0; c < 4; ++c) {
            float s = *(const float*)(sm + SS_OFF + ((0 * 4 + c) * 64 + t) * 4)
                    + *(const float*)(sm + SS_OFF + ((1 * 4 + c) * 64 + t) * 4);
            p *= rsqrtf(s * 0.015625f + 1e-6f);
        }
        *(float*)(sm + RINV_OFF + t * 4) = p;
    }
    {
        const int o = t >> 1, rh = (t & 1) * 32;
        const float* fob = fo + (size_t)n * 8192 + o;
#pragma unroll
        for (int u = 0; u < 8; ++u) {
            const int r0 = rh + u * 4;
            uint2 hi;
            hi.x = packh2(fob[(r0 + 0) * 128], fob[(r0 + 1) * 128]);
            hi.y = packh2(fob[(r0 + 2) * 128], fob[(r0 + 3) * 128]);
            *(uint2*)(sm + FOH_OFF + o * 144 + r0 * 2) = hi;
        }
    }
    __syncthreads();

    // merged = prod_c P * rinvprod  -> fp16 tile [b][r] (hi only)
    {
        const float r0v = *(const float*)(sm + RINV_OFF + (bb + g) * 4);
        const float r1v = *(const float*)(sm + RINV_OFF + (bb + g + 8) * 4);
#pragma unroll
        for (int nt = 0; nt < 4; ++nt) {
            const int rc = ws * 32 + nt * 8 + tg * 2;
            float m0 = acc[0][nt][0] * acc[1][nt][0] * acc[2][nt][0] * acc[3][nt][0] * r0v;
            float m1 = acc[0][nt][1] * acc[1][nt][1] * acc[2][nt][1] * acc[3][nt][1] * r0v;
            float m2 = acc[0][nt][2] * acc[1][nt][2] * acc[2][nt][2] * acc[3][nt][2] * r1v;
            float m3 = acc[0][nt][3] * acc[1][nt][3] * acc[2][nt][3] * acc[3][nt][3] * r1v;
            *(uint32_t*)(sm + MH_OFF + (bb + g) * 144 + rc * 2)     = packh2(m0, m1);
            *(uint32_t*)(sm + MH_OFF + (bb + g + 8) * 144 + rc * 2) = packh2(m2, m3);
        }
    }
    __syncthreads();

    // output GEMM: warp (wb, ws): 16b x 64o, K=64, 1 term (mh x foh)
    float acc2[8][4];
#pragma unroll
    for (int nt = 0; nt < 8; ++nt)
#pragma unroll
        for (int u = 0; u < 4; ++u) acc2[nt][u] = 0.0f;

    const int obase = ws * 64;
    const uint32_t mBase  = smb + MH_OFF + (uint32_t)(bb + (lane & 15)) * 144
                            + (uint32_t)((lane >> 4) << 4);
    const uint32_t foRow  = (uint32_t)(obase + (lane & 7) + ((lane >> 4) & 1) * 8);
    const uint32_t foBase = smb + FOH_OFF + foRow * 144 + (uint32_t)(((lane >> 3) & 1) << 4);

#pragma unroll
    for (int kk = 0; kk < 4; ++kk) {
        uint32_t ah[4];
        ldm_x4(ah, mBase + kk * 32);
#pragma unroll
        for (int p = 0; p < 4; ++p) {
            uint32_t bq[4];
            ldm_x4(bq, foBase + (uint32_t)(p * 16 * 144) + kk * 32);
            mma_f16(acc2[2 * p],     ah, bq);
            mma_f16(acc2[2 * p + 1], ah, bq + 2);
        }
    }

    // store with residual mean (res from smem accumulator)
#pragma unroll
    for (int nt = 0; nt < 8; ++nt) {
        const int oc = obase + nt * 8 + tg * 2;
        const int b0 = bb + g, b1 = bb + g + 8;
        const float2 r0 = *(const float2*)(sm + RES_OFF + (b0 * 128 + oc) * 4);
        const float2 r1 = *(const float2*)(sm + RES_OFF + (b1 * 128 + oc) * 4);
        float2 o0, o1;
        o0.x = acc2[nt][0] + 0.25f * r0.x;
        o0.y = acc2[nt][1] + 0.25f * r0.y;
        o1.x = acc2[nt][2] + 0.25f * r1.x;
        o1.y = acc2[nt][3] + 0.25f * r1.y;
        *(float2*)(out + ((size_t)b0 * NN + n) * 128 + oc) = o0;
        *(float2*)(out + ((size_t)b1 * NN + n) * 128 + oc) = o1;
    }
}

extern "C" void kernel_launch(void* const* d_in, const int* in_sizes, int n_in,
                              void* d_out, int out_size)
{
    const float* x       = (const float*)d_in[0];
    const float* factors = (const float*)d_in[1];
    const float* fo      = (const float*)d_in[2];
    const float* gain    = (const float*)d_in[3];
    float* out = (float*)d_out;

    cudaFuncSetAttribute(cpquad_mma13, cudaFuncAttributeMaxDynamicSharedMemorySize, SMEM_BYTES);
    cpquad_mma13<<<NN, 256, SMEM_BYTES>>>(x, factors, fo, gain, out);
}